// round 5
// baseline (speedup 1.0000x reference)
#include <cuda_runtime.h>
#include <cuda_fp16.h>
#include <cstdint>

// ============================================================================
// y = x @ W_binT - rowmean(y),  B=131072, IN=OUT=256.
// Trick 1: fold mean into weights: W' = W_bin - c/256 (EXACT in fp16: n/256).
// Trick 2: single fp16 pass for x (rel err ~2e-4 << 1e-3).
// R5: 512 threads / 16 warps (occ 12.6%->25%) -- R4 ncu showed no saturated
//     pipe (tensor 42%, L1 51%, DRAM 40%) with issue=10%: latency-bound.
//     Warp tile 64x32; x converted to fp16 at LDG time to fit 128-reg budget.
// ============================================================================

static constexpr int INF    = 256;
static constexpr int OUTF   = 256;
static constexpr int BATCH  = 131072;
static constexpr int MTILE  = 128;
static constexpr int NTILES = BATCH / MTILE;   // 1024
static constexpr int GRID   = 148;
static constexpr int THREADS = 512;

static constexpr int PW = 264;   // W smem pitch (halfs), conflict-free for ldmatrix
static constexpr int PA = 72;    // A smem pitch (halfs), conflict-free for ldmatrix
static constexpr int WBYTES = OUTF * PW * 2;        // 135168
static constexpr int ABYTES = MTILE * PA * 2;       // 18432
static constexpr int SMEM_TOTAL = WBYTES + 2 * ABYTES;  // 172032

__device__ __half g_wprep[OUTF * PW];   // mean-folded W', padded layout

// ---------------------------------------------------------------------------
// fused prep: one block per input column i.
// ---------------------------------------------------------------------------
__global__ void prep_k(const float* __restrict__ w) {
    __shared__ int red[256];
    const int i = blockIdx.x, t = threadIdx.x;
    const int bin = (w[t * INF + i] > 0.8f) ? 1 : 0;
    red[t] = bin;
    __syncthreads();
    #pragma unroll
    for (int s = 128; s > 0; s >>= 1) {
        if (t < s) red[t] += red[t + s];
        __syncthreads();
    }
    const float v = (float)bin - (float)red[0] * (1.0f / 256.0f);
    g_wprep[t * PW + i] = __float2half_rn(v);
}

// ---------------------------------------------------------------------------
// main GEMM
// ---------------------------------------------------------------------------
#define MMA_F16(c, a, b0, b1)                                                  \
    asm volatile(                                                              \
        "mma.sync.aligned.m16n8k16.row.col.f32.f16.f16.f32 "                   \
        "{%0,%1,%2,%3},{%4,%5,%6,%7},{%8,%9},{%0,%1,%2,%3};"                   \
        : "+f"((c)[0]), "+f"((c)[1]), "+f"((c)[2]), "+f"((c)[3])               \
        : "r"((a)[0]), "r"((a)[1]), "r"((a)[2]), "r"((a)[3]),                  \
          "r"(b0), "r"(b1))

#define LDSM4(r, addr)                                                         \
    asm volatile("ldmatrix.sync.aligned.m8n8.x4.shared.b16 {%0,%1,%2,%3}, [%4];" \
        : "=r"((r)[0]), "=r"((r)[1]), "=r"((r)[2]), "=r"((r)[3]) : "r"(addr))

__global__ void __launch_bounds__(THREADS, 1)
bgemm_kernel(const float* __restrict__ x, float* __restrict__ out)
{
    extern __shared__ char smem[];
    const int tid  = threadIdx.x;
    const int lane = tid & 31;
    const int wid  = tid >> 5;
    const int wm   = (wid & 1) * 64;    // warp m-offset (2-way)
    const int wn   = (wid >> 1) * 32;   // warp n-offset (8-way)

    // ---- resident W' into smem (whole kernel lifetime)
    {
        const uint4* src = reinterpret_cast<const uint4*>(g_wprep);
        uint4* dst = reinterpret_cast<uint4*>(smem);
        for (int idx = tid; idx < WBYTES / 16; idx += THREADS)
            dst[idx] = src[idx];
    }

    uint32_t sb;
    asm("{ .reg .u64 t; cvta.to.shared.u64 t, %1; cvt.u32.u64 %0, t; }"
        : "=r"(sb) : "l"(smem));
    const uint32_t ABUF[2] = { sb + WBYTES, sb + WBYTES + ABYTES };

    // per-thread ldmatrix source offsets (bytes)
    const uint32_t aoff =
        (uint32_t)((wm + (lane & 15)) * PA + (lane >> 4) * 8) * 2u;
    const uint32_t boff =
        (uint32_t)((wn + ((lane >> 4) & 1) * 8 + (lane & 7)) * PW +
                   ((lane >> 3) & 1) * 8) * 2u;

    // flat-index x mapping: 2048 float4s per 128x64 chunk, 512 threads ->
    // 4 float4/thread: row = (tid>>4) + 32*j, col4 = tid&15.
    const int arow0 = tid >> 4;         // 0..31
    const int acol4 = tid & 15;         // 0..15

    uint32_t xh[8];   // 4 rows x 4 halves-pairs (fp16x2), converted at load

    auto ldg_chunk = [&](int nt, int nc) {
        if (nt < NTILES) {
            const float* gp = x + ((size_t)nt * MTILE + arow0) * INF
                               + nc * 64 + acol4 * 4;
            #pragma unroll
            for (int j = 0; j < 4; ++j) {
                float4 v;
                asm volatile("ld.global.cs.v4.f32 {%0,%1,%2,%3}, [%4];"
                             : "=f"(v.x), "=f"(v.y), "=f"(v.z), "=f"(v.w)
                             : "l"(gp + (size_t)j * 32 * INF));
                asm("cvt.rn.f16x2.f32 %0, %1, %2;" : "=r"(xh[2*j])   : "f"(v.y), "f"(v.x));
                asm("cvt.rn.f16x2.f32 %0, %1, %2;" : "=r"(xh[2*j+1]) : "f"(v.w), "f"(v.z));
            }
        }
    };
    auto sts_chunk = [&](uint32_t ab) {
        const uint32_t base = ab + (uint32_t)(arow0 * PA + acol4 * 4) * 2u;
        #pragma unroll
        for (int j = 0; j < 4; ++j)
            asm volatile("st.shared.v2.b32 [%0], {%1,%2};"
                         :: "r"(base + (uint32_t)(j * 32 * PA) * 2u),
                            "r"(xh[2*j]), "r"(xh[2*j+1]));
    };

    // prologue: chunk0 -> buf0; preload chunk1 regs
    ldg_chunk(blockIdx.x, 0);
    sts_chunk(ABUF[0]);
    ldg_chunk(blockIdx.x, 1);
    __syncthreads();

    for (int tile = blockIdx.x; tile < NTILES; tile += GRID) {
        float acc[4][4][4];
        #pragma unroll
        for (int a = 0; a < 4; ++a)
            #pragma unroll
            for (int b = 0; b < 4; ++b)
                #pragma unroll
                for (int q = 0; q < 4; ++q) acc[a][b][q] = 0.0f;

        #pragma unroll
        for (int ch = 0; ch < 4; ++ch) {
            // STS chunk ch+1 (regs already loaded) into the other buffer
            const bool has_next = !(ch == 3 && tile + GRID >= NTILES);
            if (has_next) sts_chunk(ABUF[(ch + 1) & 1]);

            // prefetch regs for chunk ch+2
            {
                int nt = tile, nc = ch + 2;
                if (nc >= 4) { nc -= 4; nt += GRID; }
                ldg_chunk(nt, nc);
            }

            // MMA over chunk ch (4 k16-steps) from buf[ch&1]
            const uint32_t AB  = ABUF[ch & 1];
            const uint32_t bko = (uint32_t)(ch * 64) * 2u;
            #pragma unroll
            for (int ks = 0; ks < 4; ++ks) {
                const uint32_t kb2 = (uint32_t)(ks * 16) * 2u;
                uint32_t bfr[2][4];
                #pragma unroll
                for (int np = 0; np < 2; ++np)
                    LDSM4(bfr[np], sb + boff + (uint32_t)(np * 16 * PW * 2) + bko + kb2);
                uint32_t af[4][4];
                #pragma unroll
                for (int mi = 0; mi < 4; ++mi)
                    LDSM4(af[mi], AB + aoff + (uint32_t)(mi * 16 * PA * 2) + kb2);
                #pragma unroll
                for (int mi = 0; mi < 4; ++mi)
                    #pragma unroll
                    for (int ni = 0; ni < 4; ++ni)
                        MMA_F16(acc[mi][ni], af[mi],
                                bfr[ni >> 1][(ni & 1) * 2],
                                bfr[ni >> 1][(ni & 1) * 2 + 1]);
            }
            __syncthreads();
        }

        // ---- epilogue: regs -> gmem (mean already folded into W')
        const int g  = lane >> 2;
        const int t4 = (lane & 3) * 2;
        #pragma unroll
        for (int mi = 0; mi < 4; ++mi) {
            size_t r0 = (size_t)(tile * MTILE + wm + mi * 16 + g) * OUTF;
            #pragma unroll
            for (int ni = 0; ni < 4; ++ni) {
                int col = wn + ni * 8 + t4;
                asm volatile("st.global.cs.v2.f32 [%0], {%1,%2};"
                             :: "l"(out + r0 + col),
                                "f"(acc[mi][ni][0]), "f"(acc[mi][ni][1]));
                asm volatile("st.global.cs.v2.f32 [%0], {%1,%2};"
                             :: "l"(out + r0 + 8 * OUTF + col),
                                "f"(acc[mi][ni][2]), "f"(acc[mi][ni][3]));
            }
        }
    }
}

// ---------------------------------------------------------------------------
extern "C" void kernel_launch(void* const* d_in, const int* in_sizes, int n_in,
                              void* d_out, int out_size) {
    const float* x = (const float*)d_in[0];
    const float* w = (const float*)d_in[1];
    if (n_in >= 2 && in_sizes[0] < in_sizes[1]) {  // defensive: x is the big one
        const float* t = x; x = w; w = t;
    }
    float* out = (float*)d_out;

    prep_k<<<256, 256>>>(w);

    cudaFuncSetAttribute(bgemm_kernel,
                         cudaFuncAttributeMaxDynamicSharedMemorySize, SMEM_TOTAL);
    bgemm_kernel<<<GRID, THREADS, SMEM_TOTAL>>>(x, out);
}